// round 14
// baseline (speedup 1.0000x reference)
#include <cuda_runtime.h>
#include <math.h>

#define B_    16
#define H_    512
#define W_    512
#define NPIX  (B_ * H_ * W_)
#define BIGF  100000000.0f
#define SENTI (1 << 28)

// ---------------- scratch (device globals; no allocation) ----------------
__device__ unsigned short g_d[NPIX];     // vertical distance (0..511; >511 => BIG)
__device__ float  g_rowsf[B_ * W_];      // f (squared) at h==b rows
__device__ int    g_maxf[B_];            // per-batch max f (float bits) [reset by k_fin]
__device__ float  g_S1[B_ * W_];         // per-column sum of (x-t)^2 over t!=0 [reset by k_fin]
__device__ double g_acc[4];              // [S0, sum_p, sum_t, sum_pt] [reset by k_fin]

// ---- static stream/events for fork-join overlap (created before harness baseline) ----
static cudaStream_t s_stream2;
static cudaEvent_t  s_evFork, s_evJoin;
static struct _InitStreams {
    _InitStreams() {
        cudaStreamCreateWithFlags(&s_stream2, cudaStreamNonBlocking);
        cudaEventCreateWithFlags(&s_evFork, cudaEventDisableTiming);
        cudaEventCreateWithFlags(&s_evJoin, cudaEventDisableTiming);
    }
} _initStreams;

// ================= K1: vertical distances (R13 best, zmask store removed) =================
// grid (16,16); block 512 = 16 warps; warp w: rows [32w,32w+32), lane = row.
__global__ void __launch_bounds__(512, 2)
k_vert(const float* __restrict__ t) {
    __shared__ int s_first[16][32];
    __shared__ int s_last[16][32];
    __shared__ unsigned short sdn[32][512];

    const int lane = threadIdx.x & 31;
    const int w    = threadIdx.x >> 5;
    const int cg   = blockIdx.x;
    const int b    = blockIdx.y;
    const int col  = cg * 32 + lane;
    const int r0   = w * 32;

    // lane loads its own row (r0+lane), cols [32cg,32cg+32): 8 independent float4
    const float4* rowp = (const float4*)(t + ((size_t)(b * H_ + r0 + lane)) * W_ + cg * 32);
    float4 v[8];
    #pragma unroll
    for (int i = 0; i < 8; ++i) v[i] = rowp[i];

    unsigned rowmask = 0u;
    #pragma unroll
    for (int i = 0; i < 8; ++i) {
        if (v[i].x == 0.0f) rowmask |= 1u << (4 * i + 0);
        if (v[i].y == 0.0f) rowmask |= 1u << (4 * i + 1);
        if (v[i].z == 0.0f) rowmask |= 1u << (4 * i + 2);
        if (v[i].w == 0.0f) rowmask |= 1u << (4 * i + 3);
    }

    // 32x32 bit transpose (verified): bit i of lane l = zero at row r0+i, col 32cg+l
    unsigned x = rowmask;
    #pragma unroll
    for (int d = 16; d > 0; d >>= 1) {
        const unsigned m = (d == 16) ? 0x0000FFFFu :
                           (d == 8)  ? 0x00FF00FFu :
                           (d == 4)  ? 0x0F0F0F0Fu :
                           (d == 2)  ? 0x33333333u : 0x55555555u;
        unsigned y = __shfl_xor_sync(0xffffffffu, x, d);
        x = (lane & d) ? ((x & ~m) | ((y & ~m) >> d))
                       : ((x &  m) | ((y &  m) << d));
    }
    const unsigned colmask = x;

    s_last[w][lane]  = colmask ? (r0 + 31 - __clz(colmask)) : -SENTI;
    s_first[w][lane] = colmask ? (r0 + __ffs(colmask) - 1)  :  SENTI;
    __syncthreads();

    int lastAbove = -SENTI, nextBelow = SENTI;
    #pragma unroll
    for (int k = 0; k < 16; ++k) {
        int ll = s_last[k][lane];
        int ff = s_first[k][lane];
        if (k < w) lastAbove = max(lastAbove, ll);
        if (k > w) nextBelow = min(nextBelow, ff);
    }

    {
        int d = min(nextBelow - (r0 + 32), 0x7FFE);
        #pragma unroll
        for (int i = 31; i >= 0; --i) {
            d = ((colmask >> i) & 1u) ? 0 : d + 1;
            sdn[i][threadIdx.x] = (unsigned short)d;
        }
    }
    unsigned short* gbase = g_d + (size_t)b * H_ * W_ + col;
    {
        int du = min((r0 - 1) - lastAbove, 0x7FFE);
        #pragma unroll
        for (int i = 0; i < 32; ++i) {
            du = ((colmask >> i) & 1u) ? 0 : du + 1;
            int dm = min(du, (int)sdn[i][threadIdx.x]);
            gbase[(size_t)(r0 + i) * W_] = (unsigned short)min(dm, 0x7FFF);
        }
    }
}

// ================= K2: row transform (warp per row) =================
__global__ void __launch_bounds__(256)
k_row() {
    __shared__ float srow[8][W_];

    const int w    = threadIdx.x >> 5;
    const int lane = threadIdx.x & 31;
    const int bh   = blockIdx.x * 8 + w;
    const int b    = bh >> 9;
    const int h    = bh & 511;

    float* sr = srow[w];
    const unsigned short* grow = g_d + (size_t)bh * W_;
    #pragma unroll
    for (int j = 0; j < 16; ++j) {
        int y = lane + 32 * j;
        int dm = grow[y];
        sr[y] = (dm > 511) ? BIGF : (float)(dm * dm);
    }
    __syncwarp();

    float m = 0.0f;
    #pragma unroll 1
    for (int j = 0; j < 16; ++j) {
        int y = lane + 32 * j;
        float best = sr[y];
        for (int r = 1; r < W_; ++r) {
            float r2 = (float)(r * r);
            if (r2 >= best) break;             // exact early termination
            int jl = y - r, jr = y + r;
            if (jl >= 0)  best = fminf(best, sr[jl] + r2);
            if (jr < W_)  best = fminf(best, sr[jr] + r2);
        }
        if (h == b) g_rowsf[b * W_ + y] = best;
        m = fmaxf(m, best);
    }
    #pragma unroll
    for (int o = 16; o > 0; o >>= 1)
        m = fmaxf(m, __shfl_down_sync(0xffffffffu, m, o));
    if (lane == 0)
        atomicMax(&g_maxf[b], __float_as_int(m));
}

// ================= K_loss: EDT-independent sums (runs on stream 2) =================
// grid (16 rowtiles, 16 batches), block 512. Thread: col4 = tid&127, rg = tid>>7.
// Covers 32 rows x 512 cols; per-thread: 8 rows of one float4-column.
__global__ void __launch_bounds__(512)
k_loss(const float4* __restrict__ in4, const float4* __restrict__ tg4) {
    __shared__ float sS1[W_];
    __shared__ float red[4][16];

    const int tid  = threadIdx.x;
    const int rt   = blockIdx.x;
    const int b    = blockIdx.y;
    const int col4 = tid & 127;
    const int rg   = tid >> 7;

    sS1[tid] = 0.f;
    __syncthreads();

    const int row0 = rt * 32 + rg * 8;
    const size_t base = ((size_t)(b * H_ + row0)) * (W_ / 4) + col4;

    float c0 = 0.f, c1 = 0.f, c2 = 0.f, c3 = 0.f;
    float s0 = 0.f, sp = 0.f, st = 0.f, spt = 0.f;

    #pragma unroll
    for (int rr = 0; rr < 8; rr += 4) {
        float4 xa[4], ta[4];
        #pragma unroll
        for (int k = 0; k < 4; ++k) {
            xa[k] = in4[base + (size_t)(rr + k) * (W_ / 4)];
            ta[k] = tg4[base + (size_t)(rr + k) * (W_ / 4)];
        }
        #pragma unroll
        for (int k = 0; k < 4; ++k) {
            float dd, d2, p;
            dd = xa[k].x - ta[k].x; d2 = dd * dd; s0 += d2; if (ta[k].x != 0.f) c0 += d2;
            p = __fdividef(1.f, 1.f + __expf(-xa[k].x)); sp += p; st += ta[k].x; spt += p * ta[k].x;
            dd = xa[k].y - ta[k].y; d2 = dd * dd; s0 += d2; if (ta[k].y != 0.f) c1 += d2;
            p = __fdividef(1.f, 1.f + __expf(-xa[k].y)); sp += p; st += ta[k].y; spt += p * ta[k].y;
            dd = xa[k].z - ta[k].z; d2 = dd * dd; s0 += d2; if (ta[k].z != 0.f) c2 += d2;
            p = __fdividef(1.f, 1.f + __expf(-xa[k].z)); sp += p; st += ta[k].z; spt += p * ta[k].z;
            dd = xa[k].w - ta[k].w; d2 = dd * dd; s0 += d2; if (ta[k].w != 0.f) c3 += d2;
            p = __fdividef(1.f, 1.f + __expf(-xa[k].w)); sp += p; st += ta[k].w; spt += p * ta[k].w;
        }
    }

    // per-column S1 into smem (conflict degree 4 across rg)
    atomicAdd(&sS1[col4 * 4 + 0], c0);
    atomicAdd(&sS1[col4 * 4 + 1], c1);
    atomicAdd(&sS1[col4 * 4 + 2], c2);
    atomicAdd(&sS1[col4 * 4 + 3], c3);

    // block reduce the 4 scalar sums
    float vals[4] = {s0, sp, st, spt};
    #pragma unroll
    for (int q = 0; q < 4; ++q) {
        float s = vals[q];
        #pragma unroll
        for (int o = 16; o > 0; o >>= 1)
            s += __shfl_down_sync(0xffffffffu, s, o);
        if ((tid & 31) == 0) red[q][tid >> 5] = s;
    }
    __syncthreads();

    atomicAdd(&g_S1[b * W_ + tid], sS1[tid]);

    if (tid < 16) {
        float a0 = red[0][tid], a1 = red[1][tid], a2 = red[2][tid], a3 = red[3][tid];
        #pragma unroll
        for (int o = 8; o > 0; o >>= 1) {
            a0 += __shfl_down_sync(0xffffu, a0, o);
            a1 += __shfl_down_sync(0xffffu, a1, o);
            a2 += __shfl_down_sync(0xffffu, a2, o);
            a3 += __shfl_down_sync(0xffffu, a3, o);
        }
        if (tid == 0) {
            atomicAdd(&g_acc[0], (double)a0);
            atomicAdd(&g_acc[1], (double)a1);
            atomicAdd(&g_acc[2], (double)a2);
            atomicAdd(&g_acc[3], (double)a3);
        }
    }
}

// ================= K_fin: combine + finalize + reset =================
__global__ void k_fin(float* __restrict__ out, int out_size) {
    __shared__ double sred[16];
    const int tid = threadIdx.x;   // 512

    double acc = 0.0;
    #pragma unroll 1
    for (int b = 0; b < B_; ++b) {
        float v  = sqrtf(__int_as_float(g_maxf[b]));
        float wb = v - sqrtf(g_rowsf[b * W_ + tid]);
        acc += (double)(wb * g_S1[b * W_ + tid]);
    }
    #pragma unroll
    for (int o = 16; o > 0; o >>= 1)
        acc += __shfl_down_sync(0xffffffffu, acc, o);
    if ((tid & 31) == 0) sred[tid >> 5] = acc;
    __syncthreads();
    if (tid == 0) {
        double wsum = 0.0;
        #pragma unroll
        for (int i = 0; i < 16; ++i) wsum += sred[i];
        double wmse = (0.001 * g_acc[0] + wsum) / (double)NPIX;
        double P = g_acc[1], T = g_acc[2], I = g_acc[3];
        double dice = 1.0 - (2.0 * I + 1e-6) / (P + T + 1e-6);
        if (out_size >= 1) out[0] = (float)(0.6 * wmse);
        if (out_size >= 2) out[1] = (float)(1.0 * dice);
    }
    __syncthreads();
    // reset state for next replay (first run relies on static zero-init)
    if (tid < 4)  g_acc[tid] = 0.0;
    if (tid < B_) g_maxf[tid] = 0;
    #pragma unroll
    for (int i = 0; i < B_ * W_ / 512; ++i)
        g_S1[i * 512 + tid] = 0.f;
}

// ---------------- launch: fork-join across two streams ----------------
extern "C" void kernel_launch(void* const* d_in, const int* in_sizes, int n_in,
                              void* d_out, int out_size) {
    const float* inputs  = (const float*)d_in[0];
    const float* targets = (const float*)d_in[1];
    float* out = (float*)d_out;

    // fork: loss pass on stream2 (no EDT dependency)
    cudaEventRecord(s_evFork, 0);
    cudaStreamWaitEvent(s_stream2, s_evFork, 0);
    dim3 gl(16, B_);
    k_loss<<<gl, 512, 0, s_stream2>>>((const float4*)inputs, (const float4*)targets);

    // EDT chain on the main stream
    dim3 gv(16, B_);
    k_vert<<<gv, 512>>>(targets);
    k_row<<<B_ * H_ / 8, 256>>>();

    // join + finalize
    cudaEventRecord(s_evJoin, s_stream2);
    cudaStreamWaitEvent(0, s_evJoin, 0);
    k_fin<<<1, 512>>>(out, out_size);
}

// round 15
// speedup vs baseline: 1.2962x; 1.2962x over previous
#include <cuda_runtime.h>
#include <math.h>

#define B_    16
#define H_    512
#define W_    512
#define NPIX  (B_ * H_ * W_)
#define BIGF  100000000.0f
#define SENTI (1 << 28)

// ---------------- scratch (device globals; no allocation) ----------------
__device__ unsigned short g_d[NPIX];     // vertical distance (0..511; >511 => BIG)
__device__ float  g_rowsf[B_ * W_];      // f (squared) at h==b rows
__device__ int    g_maxf[B_];            // per-batch max f (float bits) [reset in k_fin]
__device__ float  g_S1[B_ * W_];         // per-column sum of (x-t)^2 over t!=0 [reset in k_fin]
__device__ double g_acc[4];              // [S0, sum_p, sum_t, sum_pt] [reset in k_fin]
__device__ double g_wsum;                // [reset in k_fin]
__device__ unsigned int g_fin_done;      // [reset in k_fin]

// ---- static stream/events for fork-join overlap ----
static cudaStream_t s_stream2;
static cudaEvent_t  s_evFork, s_evJoin;
static struct _InitStreams {
    _InitStreams() {
        cudaStreamCreateWithFlags(&s_stream2, cudaStreamNonBlocking);
        cudaEventCreateWithFlags(&s_evFork, cudaEventDisableTiming);
        cudaEventCreateWithFlags(&s_evJoin, cudaEventDisableTiming);
    }
} _initStreams;

// ================= K1: vertical distances =================
// grid (16,16); block 512 = 16 warps; warp w: rows [32w,32w+32), lane = row.
__global__ void __launch_bounds__(512, 2)
k_vert(const float* __restrict__ t) {
    __shared__ int s_first[16][32];
    __shared__ int s_last[16][32];
    __shared__ unsigned short sdn[32][512];

    const int lane = threadIdx.x & 31;
    const int w    = threadIdx.x >> 5;
    const int cg   = blockIdx.x;
    const int b    = blockIdx.y;
    const int col  = cg * 32 + lane;
    const int r0   = w * 32;

    const float4* rowp = (const float4*)(t + ((size_t)(b * H_ + r0 + lane)) * W_ + cg * 32);
    float4 v[8];
    #pragma unroll
    for (int i = 0; i < 8; ++i) v[i] = rowp[i];

    unsigned rowmask = 0u;
    #pragma unroll
    for (int i = 0; i < 8; ++i) {
        if (v[i].x == 0.0f) rowmask |= 1u << (4 * i + 0);
        if (v[i].y == 0.0f) rowmask |= 1u << (4 * i + 1);
        if (v[i].z == 0.0f) rowmask |= 1u << (4 * i + 2);
        if (v[i].w == 0.0f) rowmask |= 1u << (4 * i + 3);
    }

    // 32x32 bit transpose: bit i of lane l = zero at row r0+i, col 32cg+l
    unsigned x = rowmask;
    #pragma unroll
    for (int d = 16; d > 0; d >>= 1) {
        const unsigned m = (d == 16) ? 0x0000FFFFu :
                           (d == 8)  ? 0x00FF00FFu :
                           (d == 4)  ? 0x0F0F0F0Fu :
                           (d == 2)  ? 0x33333333u : 0x55555555u;
        unsigned y = __shfl_xor_sync(0xffffffffu, x, d);
        x = (lane & d) ? ((x & ~m) | ((y & ~m) >> d))
                       : ((x &  m) | ((y &  m) << d));
    }
    const unsigned colmask = x;

    s_last[w][lane]  = colmask ? (r0 + 31 - __clz(colmask)) : -SENTI;
    s_first[w][lane] = colmask ? (r0 + __ffs(colmask) - 1)  :  SENTI;
    __syncthreads();

    int lastAbove = -SENTI, nextBelow = SENTI;
    #pragma unroll
    for (int k = 0; k < 16; ++k) {
        int ll = s_last[k][lane];
        int ff = s_first[k][lane];
        if (k < w) lastAbove = max(lastAbove, ll);
        if (k > w) nextBelow = min(nextBelow, ff);
    }

    {
        int d = min(nextBelow - (r0 + 32), 0x7FFE);
        #pragma unroll
        for (int i = 31; i >= 0; --i) {
            d = ((colmask >> i) & 1u) ? 0 : d + 1;
            sdn[i][threadIdx.x] = (unsigned short)d;
        }
    }
    unsigned short* gbase = g_d + (size_t)b * H_ * W_ + col;
    {
        int du = min((r0 - 1) - lastAbove, 0x7FFE);
        #pragma unroll
        for (int i = 0; i < 32; ++i) {
            du = ((colmask >> i) & 1u) ? 0 : du + 1;
            int dm = min(du, (int)sdn[i][threadIdx.x]);
            gbase[(size_t)(r0 + i) * W_] = (unsigned short)min(dm, 0x7FFF);
        }
    }
}

// ================= K2: row transform (warp per row) =================
__global__ void __launch_bounds__(256)
k_row() {
    __shared__ float srow[8][W_];

    const int w    = threadIdx.x >> 5;
    const int lane = threadIdx.x & 31;
    const int bh   = blockIdx.x * 8 + w;
    const int b    = bh >> 9;
    const int h    = bh & 511;

    float* sr = srow[w];
    const unsigned short* grow = g_d + (size_t)bh * W_;
    #pragma unroll
    for (int j = 0; j < 16; ++j) {
        int y = lane + 32 * j;
        int dm = grow[y];
        sr[y] = (dm > 511) ? BIGF : (float)(dm * dm);
    }
    __syncwarp();

    float m = 0.0f;
    #pragma unroll 1
    for (int j = 0; j < 16; ++j) {
        int y = lane + 32 * j;
        float best = sr[y];
        for (int r = 1; r < W_; ++r) {
            float r2 = (float)(r * r);
            if (r2 >= best) break;             // exact early termination
            int jl = y - r, jr = y + r;
            if (jl >= 0)  best = fminf(best, sr[jl] + r2);
            if (jr < W_)  best = fminf(best, sr[jr] + r2);
        }
        if (h == b) g_rowsf[b * W_ + y] = best;
        m = fmaxf(m, best);
    }
    #pragma unroll
    for (int o = 16; o > 0; o >>= 1)
        m = fmaxf(m, __shfl_down_sync(0xffffffffu, m, o));
    if (lane == 0)
        atomicMax(&g_maxf[b], __float_as_int(m));
}

// ================= K_loss: EDT-independent sums (stream 2) =================
// grid (16 rowtiles, 16 batches), block 512.
__global__ void __launch_bounds__(512)
k_loss(const float4* __restrict__ in4, const float4* __restrict__ tg4) {
    __shared__ float sS1[W_];
    __shared__ float red[4][16];

    const int tid  = threadIdx.x;
    const int rt   = blockIdx.x;
    const int b    = blockIdx.y;
    const int col4 = tid & 127;
    const int rg   = tid >> 7;

    sS1[tid] = 0.f;
    __syncthreads();

    const int row0 = rt * 32 + rg * 8;
    const size_t base = ((size_t)(b * H_ + row0)) * (W_ / 4) + col4;

    float c0 = 0.f, c1 = 0.f, c2 = 0.f, c3 = 0.f;
    float s0 = 0.f, sp = 0.f, st = 0.f, spt = 0.f;

    #pragma unroll
    for (int rr = 0; rr < 8; rr += 4) {
        float4 xa[4], ta[4];
        #pragma unroll
        for (int k = 0; k < 4; ++k) {
            xa[k] = in4[base + (size_t)(rr + k) * (W_ / 4)];
            ta[k] = tg4[base + (size_t)(rr + k) * (W_ / 4)];
        }
        #pragma unroll
        for (int k = 0; k < 4; ++k) {
            float dd, d2, p;
            dd = xa[k].x - ta[k].x; d2 = dd * dd; s0 += d2; if (ta[k].x != 0.f) c0 += d2;
            p = __fdividef(1.f, 1.f + __expf(-xa[k].x)); sp += p; st += ta[k].x; spt += p * ta[k].x;
            dd = xa[k].y - ta[k].y; d2 = dd * dd; s0 += d2; if (ta[k].y != 0.f) c1 += d2;
            p = __fdividef(1.f, 1.f + __expf(-xa[k].y)); sp += p; st += ta[k].y; spt += p * ta[k].y;
            dd = xa[k].z - ta[k].z; d2 = dd * dd; s0 += d2; if (ta[k].z != 0.f) c2 += d2;
            p = __fdividef(1.f, 1.f + __expf(-xa[k].z)); sp += p; st += ta[k].z; spt += p * ta[k].z;
            dd = xa[k].w - ta[k].w; d2 = dd * dd; s0 += d2; if (ta[k].w != 0.f) c3 += d2;
            p = __fdividef(1.f, 1.f + __expf(-xa[k].w)); sp += p; st += ta[k].w; spt += p * ta[k].w;
        }
    }

    atomicAdd(&sS1[col4 * 4 + 0], c0);
    atomicAdd(&sS1[col4 * 4 + 1], c1);
    atomicAdd(&sS1[col4 * 4 + 2], c2);
    atomicAdd(&sS1[col4 * 4 + 3], c3);

    float vals[4] = {s0, sp, st, spt};
    #pragma unroll
    for (int q = 0; q < 4; ++q) {
        float s = vals[q];
        #pragma unroll
        for (int o = 16; o > 0; o >>= 1)
            s += __shfl_down_sync(0xffffffffu, s, o);
        if ((tid & 31) == 0) red[q][tid >> 5] = s;
    }
    __syncthreads();

    atomicAdd(&g_S1[b * W_ + tid], sS1[tid]);

    if (tid < 16) {
        float a0 = red[0][tid], a1 = red[1][tid], a2 = red[2][tid], a3 = red[3][tid];
        #pragma unroll
        for (int o = 8; o > 0; o >>= 1) {
            a0 += __shfl_down_sync(0xffffu, a0, o);
            a1 += __shfl_down_sync(0xffffu, a1, o);
            a2 += __shfl_down_sync(0xffffu, a2, o);
            a3 += __shfl_down_sync(0xffffu, a3, o);
        }
        if (tid == 0) {
            atomicAdd(&g_acc[0], (double)a0);
            atomicAdd(&g_acc[1], (double)a1);
            atomicAdd(&g_acc[2], (double)a2);
            atomicAdd(&g_acc[3], (double)a3);
        }
    }
}

// ================= K_fin: parallel combine + finalize + reset =================
// grid 16 (block per batch), block 512.
__global__ void __launch_bounds__(512)
k_fin(float* __restrict__ out, int out_size) {
    __shared__ double sred[16];
    __shared__ bool s_lastb;
    const int tid = threadIdx.x;
    const int b   = blockIdx.x;

    const float v  = sqrtf(__int_as_float(g_maxf[b]));
    const float wb = v - sqrtf(g_rowsf[b * W_ + tid]);
    double acc = (double)(wb * g_S1[b * W_ + tid]);
    g_S1[b * W_ + tid] = 0.f;                     // reset own slice

    #pragma unroll
    for (int o = 16; o > 0; o >>= 1)
        acc += __shfl_down_sync(0xffffffffu, acc, o);
    if ((tid & 31) == 0) sred[tid >> 5] = acc;
    __syncthreads();
    if (tid < 16) {
        double a = sred[tid];
        #pragma unroll
        for (int o = 8; o > 0; o >>= 1)
            a += __shfl_down_sync(0xffffu, a, o);
        if (tid == 0) {
            atomicAdd(&g_wsum, a);
            __threadfence();
            unsigned n = atomicAdd(&g_fin_done, 1u);
            s_lastb = (n == B_ - 1u);
        }
    }
    __syncthreads();
    if (s_lastb) {
        if (tid == 0) {
            __threadfence();
            double wmse = (0.001 * g_acc[0] + g_wsum) / (double)NPIX;
            double P = g_acc[1], T = g_acc[2], I = g_acc[3];
            double dice = 1.0 - (2.0 * I + 1e-6) / (P + T + 1e-6);
            if (out_size >= 1) out[0] = (float)(0.6 * wmse);
            if (out_size >= 2) out[1] = (float)(1.0 * dice);
            // reset small state for next replay
            g_wsum = 0.0;
            g_fin_done = 0u;
            #pragma unroll
            for (int q = 0; q < 4; ++q) g_acc[q] = 0.0;
            #pragma unroll
            for (int q = 0; q < B_; ++q) g_maxf[q] = 0;
        }
    }
}

// ---------------- launch: fork-join across two streams ----------------
extern "C" void kernel_launch(void* const* d_in, const int* in_sizes, int n_in,
                              void* d_out, int out_size) {
    const float* inputs  = (const float*)d_in[0];
    const float* targets = (const float*)d_in[1];
    float* out = (float*)d_out;

    // fork: loss pass on stream2 (no EDT dependency)
    cudaEventRecord(s_evFork, 0);
    cudaStreamWaitEvent(s_stream2, s_evFork, 0);
    dim3 gl(16, B_);
    k_loss<<<gl, 512, 0, s_stream2>>>((const float4*)inputs, (const float4*)targets);

    // EDT chain on the main stream
    dim3 gv(16, B_);
    k_vert<<<gv, 512>>>(targets);
    k_row<<<B_ * H_ / 8, 256>>>();

    // join + finalize
    cudaEventRecord(s_evJoin, s_stream2);
    cudaStreamWaitEvent(0, s_evJoin, 0);
    k_fin<<<B_, 512>>>(out, out_size);
}